// round 15
// baseline (speedup 1.0000x reference)
#include <cuda_runtime.h>
#include <cuda_fp16.h>
#include <cstdint>
#include <cstddef>

#define S_LEN 512

// mma-fragment-linear weights (u32 lane-regs). For mat,k-tile q,n-tile t:
// u32 at base + (q*16 + t)*64 + lane*2 + r holds halves {W[j][k0], W[j][k0+1]}
// with j = t*8 + lane/4, k0 = q*16 + r*8 + 2*(lane%4).
#define MM_WG0H  0
#define MM_WREC0 8192
#define MM_WIN1  16384
#define MM_WG1X  24576
#define MM_WG1H  32768
#define MM_WREC1 40960
#define MM_WIN0S 49152
#define MM_WG0S  53248
#define MM_TOTAL 57344

__device__ __align__(16) uint32_t g_Wm[MM_TOTAL];
// ctx mats fp32 row-major [j][32]: [0]=Win0 ctx part, [4096]=Wg0 ctx part
__device__ __align__(16) float g_Wc[2 * 4096];

#define HSTB 272  // h smem row stride bytes (136 halves)
#define XSTB 144  // x smem row stride bytes (72 halves)
#define DUPH (12 * HSTB)
#define DUPX (12 * XSTB)

__device__ __forceinline__ float sigm(float x) {
    return __fdividef(1.0f, 1.0f + __expf(-x));
}
__device__ __forceinline__ float fast_tanh(float x) {
    float ax = fabsf(x);
    float e = __expf(ax + ax);
    float t = 1.0f - __fdividef(2.0f, e + 1.0f);
    return copysignf(t, x);
}
// gate = sigmoid(tanh(z)); sigmoid of t in [-1,1] via degree-7 odd polynomial
__device__ __forceinline__ float gate_fn(float z) {
    float t = fast_tanh(z);
    float t2 = t * t;
    float p = fmaf(t2, -2.00134e-4f, 2.0833333e-3f);
    p = fmaf(t2, p, -2.0833334e-2f);
    p = fmaf(t2, p, 0.25f);
    return fmaf(t, p, 0.5f);
}

// ---------------- weight prep: fragment-linear fp16 + fp32 ctx ----------------
__global__ void __launch_bounds__(256) prep_weights(
    const float* __restrict__ Win0, const float* __restrict__ Wg0,
    const float* __restrict__ Wrec0, const float* __restrict__ Win1,
    const float* __restrict__ Wrec1, const float* __restrict__ Wg1) {
    int idx = blockIdx.x * 256 + threadIdx.x;
    if (idx < MM_TOTAL) {
        int mat, rem;
        if (idx < 49152) {
            mat = idx >> 13;
            rem = idx & 8191;
        } else {
            mat = 6 + ((idx - 49152) >> 12);
            rem = (idx - 49152) & 4095;
        }
        int q = rem >> 10;
        int rr = rem & 1023;
        int t = rr >> 6;
        int le = rr & 63;
        int l = le >> 1, r = le & 1;
        int j = t * 8 + (l >> 2);
        int k = q * 16 + (r << 3) + 2 * (l & 3);
        float f0, f1;
        switch (mat) {
            case 0: f0 = Wg0[j * 224 + 96 + k]; f1 = Wg0[j * 224 + 97 + k]; break;
            case 1: f0 = Wrec0[j * 128 + k]; f1 = Wrec0[j * 128 + k + 1]; break;
            case 2: f0 = Win1[j * 128 + k]; f1 = Win1[j * 128 + k + 1]; break;
            case 3: f0 = Wg1[j * 256 + k]; f1 = Wg1[j * 256 + k + 1]; break;
            case 4: f0 = Wg1[j * 256 + 128 + k]; f1 = Wg1[j * 256 + 129 + k]; break;
            case 5: f0 = Wrec1[j * 128 + k]; f1 = Wrec1[j * 128 + k + 1]; break;
            case 6: f0 = Win0[j * 96 + k]; f1 = Win0[j * 96 + k + 1]; break;
            default: f0 = Wg0[j * 224 + k]; f1 = Wg0[j * 224 + k + 1]; break;
        }
        uint32_t u = (uint32_t)__half_as_ushort(__float2half_rn(f0)) |
                     ((uint32_t)__half_as_ushort(__float2half_rn(f1)) << 16);
        g_Wm[idx] = u;
    } else if (idx < MM_TOTAL + 8192) {
        int r2 = idx - MM_TOTAL;
        int m = r2 >> 12, a = r2 & 4095;
        int j = a >> 5, k = a & 31;
        g_Wc[r2] = m ? Wg0[j * 224 + 64 + k] : Win0[j * 96 + 64 + k];
    }
}

// ---------------- mma primitives ----------------
__device__ __forceinline__ void ldsm4(uint32_t addr, uint32_t& r0, uint32_t& r1,
                                      uint32_t& r2, uint32_t& r3) {
    asm volatile("ldmatrix.sync.aligned.m8n8.x4.shared.b16 {%0,%1,%2,%3}, [%4];"
                 : "=r"(r0), "=r"(r1), "=r"(r2), "=r"(r3)
                 : "r"(addr));
}
__device__ __forceinline__ void mma16816(float* c, uint32_t a0, uint32_t a1,
                                         uint32_t a2, uint32_t a3, uint32_t b0,
                                         uint32_t b1) {
    asm volatile(
        "mma.sync.aligned.m16n8k16.row.col.f32.f16.f16.f32 "
        "{%0,%1,%2,%3}, {%4,%5,%6,%7}, {%8,%9}, {%0,%1,%2,%3};"
        : "+f"(c[0]), "+f"(c[1]), "+f"(c[2]), "+f"(c[3])
        : "r"(a0), "r"(a1), "r"(a2), "r"(a3), "r"(b0), "r"(b1));
}

// Group dual-matmul phase: warp covers n-tiles {2*wg, 2*wg+1} of both mats
// (wb has the 2*wg fold). X[16][K] fp16 in smem; B frags via LDG.64. KT = K/16.
template <int KT, int OFFA, int OFFB>
__device__ __forceinline__ void mma_phase_g(const uint32_t* __restrict__ wb,
                                            uint32_t aaddr, float cA[2][4],
                                            float cB[2][4]) {
#pragma unroll
    for (int q = 0; q < KT; ++q) {
        uint32_t a0, a1, a2, a3;
        ldsm4(aaddr + q * 32, a0, a1, a2, a3);
#pragma unroll
        for (int t = 0; t < 2; ++t) {
            uint2 bA = *reinterpret_cast<const uint2*>(wb + OFFA + (q * 16 + t) * 64);
            uint2 bB = *reinterpret_cast<const uint2*>(wb + OFFB + (q * 16 + t) * 64);
            mma16816(cA[t], a0, a1, a2, a3, bA.x, bA.y);
            mma16816(cB[t], a0, a1, a2, a3, bB.x, bB.y);
        }
    }
}

// Slot extraction: A-operand rows 0-3 and 12-15 hold duplicated batches, so
// low lanes read c[t][0..1] (rows 0-3) and high lanes c[t][2..3] (rows 12-15).
__device__ __forceinline__ float csel(const float c[2][4], bool hi, int i) {
    return c[i >> 1][(hi ? 2 : 0) + (i & 1)];
}

// RK4 for one cell run by ONE 256-thread group (named barrier BARID). Every
// lane owns 4 (batch, j) slots; new h stored to row b and dup row 12+b.
template <int OFFG, int OFFR, int BARID>
__device__ __forceinline__ void rk4_g(const uint32_t* __restrict__ wb,
                                      const float* it, const float* xin,
                                      const float* xg, float* hst, char* nb0,
                                      char* nb1, const uint32_t aaddr[2], int& cu,
                                      bool hi, int hoff, char* hout) {
    float ka[4] = {0, 0, 0, 0};
    float ht[4] = {hst[0], hst[1], hst[2], hst[3]};
#pragma unroll
    for (int sub = 0; sub < 4; ++sub) {
        float cg[2][4] = {}, cr[2][4] = {};
        mma_phase_g<8, OFFG, OFFR>(wb, aaddr[cu], cg, cr);
        const float kw = (sub == 0 || sub == 3) ? 1.f : 2.f;
        const float cv = (sub < 2) ? 0.5f : 1.f;
        char* dst = cu ? nb0 : nb1;  // next buffer = cu^1
#pragma unroll
        for (int tt = 0; tt < 2; ++tt) {
            float nh2[2];
#pragma unroll
            for (int s2 = 0; s2 < 2; ++s2) {
                const int i = tt * 2 + s2;
                float gate = gate_fn(csel(cg, hi, i) + xg[i]);
                float kv = fmaf(gate, csel(cr, hi, i), fmaf(-ht[i], it[i], xin[i]));
                ka[i] = fmaf(kw, kv, ka[i]);
                float nh = (sub < 3) ? fmaf(cv, kv, hst[i])
                                     : fast_tanh(fmaf(ka[i], 0.16666667f, hst[i]));
                ht[i] = nh;
                nh2[s2] = nh;
            }
            __half2 hv = __floats2half2_rn(nh2[0], nh2[1]);
            *reinterpret_cast<__half2*>(dst + hoff + tt * 16) = hv;
            *reinterpret_cast<__half2*>(dst + hoff + tt * 16 + DUPH) = hv;
            if (sub == 3 && hout) {
                *reinterpret_cast<__half2*>(hout + hoff + tt * 16) = hv;
                *reinterpret_cast<__half2*>(hout + hoff + tt * 16 + DUPH) = hv;
            }
        }
        asm volatile("bar.sync %0, 256;" ::"r"(BARID) : "memory");
        cu ^= 1;
    }
#pragma unroll
    for (int i = 0; i < 4; ++i) hst[i] = ht[i];
}

// ---------------- persistent recurrence: 128 CTAs x 512 threads ----------------
// Warp-specialized cell pipeline: warps 0-7 (group A, bar 1) run the cell-0
// chain; warps 8-15 (group B, bar 2) run cell-1 one step behind, consuming h0
// via a parity double-buffer. Within a group, warp wg owns n-tiles
// {2*wg, 2*wg+1} = j in [wg*16, wg*16+16). A-operand rows 0-3 / 12-15 hold
// duplicated batches so all 32 lanes get valid C fragments (4 slots each).
__global__ void __launch_bounds__(512, 1)
ltc_recurrent(const float* __restrict__ seq, const float* __restrict__ ctx,
              const float* __restrict__ tau0, const float* __restrict__ bg0,
              const float* __restrict__ tau1, const float* __restrict__ bg1,
              const float* __restrict__ W1, const float* __restrict__ b1,
              const float* __restrict__ W2, const float* __restrict__ b2,
              float* __restrict__ out) {
    __shared__ __align__(16) __half hA[2][16 * 136];   // cell-0 RK4 ping-pong
    __shared__ __align__(16) __half hB[2][16 * 136];   // cell-1 RK4 ping-pong
    __shared__ __align__(16) __half h0o[2][16 * 136];  // A->B handoff (parity)
    __shared__ __align__(16) __half xsm[2][16 * 72];   // x double buffer
    __shared__ __align__(16) float xcf[128];
    __shared__ __align__(16) float st0[512];
    const int tid = threadIdx.x, lane = tid & 31;
    const bool isA = tid < 256;
    const int wg = (tid >> 5) & 7;
    const int b0g = blockIdx.x * 4;
    const bool hi = lane >= 16;
    const int b = (lane & 15) >> 2;

    // zero all fp16 A-operand buffers (rows 4-11 stay zero = M padding)
    {
        __half z = __float2half(0.f);
        for (int i = tid; i < 2 * 16 * 136; i += 512) {
            reinterpret_cast<__half*>(hA)[i] = z;
            reinterpret_cast<__half*>(hB)[i] = z;
            reinterpret_cast<__half*>(h0o)[i] = z;
        }
        for (int i = tid; i < 2 * 16 * 72; i += 512)
            reinterpret_cast<__half*>(xsm)[i] = z;
    }
    if (tid < 128) xcf[tid] = ctx[(size_t)(b0g + (tid >> 5)) * 32 + (tid & 31)];
    __syncthreads();

    // per-lane params: 4 slots i -> j = wg*16 + (i>>1)*8 + 2*(lane&3) + (i&1)
    float its[4], xinc[4] = {0, 0, 0, 0}, xgc[4] = {0, 0, 0, 0};
    const int hoff = b * HSTB + (wg * 16 + 2 * (lane & 3)) * 2;
#pragma unroll
    for (int i = 0; i < 4; ++i) {
        int j = wg * 16 + (i >> 1) * 8 + 2 * (lane & 3) + (i & 1);
        const float* taup = isA ? tau0 : tau1;
        its[i] = __fdividef(1.f, log1pf(__expf(taup[j])) + 1.f);
        if (isA) {
            float ai = 0.f, ag = 0.f;
            for (int k = 0; k < 32; ++k) {
                float xv = xcf[b * 32 + k];
                ai = fmaf(xv, __ldg(&g_Wc[j * 32 + k]), ai);
                ag = fmaf(xv, __ldg(&g_Wc[4096 + j * 32 + k]), ag);
            }
            xinc[i] = ai;
            xgc[i] = ag + bg0[j];
        } else {
            xgc[i] = bg1[j];  // xgc = bg1 bias for group B
        }
    }

    // x staging: A threads 0-127 stage one half2 each (+ dup row)
    const int xb = (tid >> 5) & 3;
    const int xk2 = tid & 31;
    const float* seqp = seq + ((size_t)(b0g + xb) * S_LEN) * 64 + 2 * xk2;
    const int xoffb = xb * XSTB + xk2 * 4;
    const bool stager = tid < 128;
    if (stager) {
        float2 v = *reinterpret_cast<const float2*>(seqp);
        __half2 hv = __floats2half2_rn(v.x, v.y);
        *reinterpret_cast<__half2*>((char*)xsm + xoffb) = hv;
        *reinterpret_cast<__half2*>((char*)xsm + xoffb + DUPX) = hv;
    }
    __syncthreads();

    // ldmatrix A addresses
    const uint32_t aoffh = (uint32_t)(lane & 15) * HSTB + (uint32_t)(lane >> 4) * 16;
    const uint32_t aoffx = (uint32_t)(lane & 15) * XSTB + (uint32_t)(lane >> 4) * 16;
    const uint32_t bA0 = (uint32_t)__cvta_generic_to_shared(hA);
    const uint32_t bB0 = (uint32_t)__cvta_generic_to_shared(hB);
    const uint32_t bH0 = (uint32_t)__cvta_generic_to_shared(h0o);
    const uint32_t bX0 = (uint32_t)__cvta_generic_to_shared(xsm);
    const uint32_t addr_hA[2] = {bA0 + aoffh, bA0 + 4352 + aoffh};
    const uint32_t addr_hB[2] = {bB0 + aoffh, bB0 + 4352 + aoffh};
    const uint32_t addr_h0[2] = {bH0 + aoffh, bH0 + 4352 + aoffh};
    const uint32_t addr_x[2] = {bX0 + aoffx, bX0 + 2304 + aoffx};

    // warp's B-fragment base: n-tiles {2*wg, 2*wg+1} folded in
    const uint32_t* wb = g_Wm + wg * 128 + lane * 2;

    float hst[4] = {0, 0, 0, 0};
    int cu = 0, p = 0;

    for (int s = 0; s <= S_LEN; ++s) {
        if (isA) {
            if (s < S_LEN) {
                // prefetch x(s+1)
                float2 xn = {0.f, 0.f};
                const bool hasn = (s + 1 < S_LEN) && stager;
                if (hasn)
                    xn = *reinterpret_cast<const float2*>(seqp + (size_t)(s + 1) * 64);
                // cell-0 input projections from x(s)
                float ci[2][4] = {}, cg[2][4] = {};
                mma_phase_g<4, MM_WIN0S, MM_WG0S>(wb, addr_x[p], ci, cg);
                float xin0[4], xg0[4];
#pragma unroll
                for (int i = 0; i < 4; ++i) {
                    xin0[i] = csel(ci, hi, i) + xinc[i];
                    xg0[i] = csel(cg, hi, i) + xgc[i];
                }
                // stage x(s+1) (readers: next step's A proj, after 4 bar-1s)
                if (hasn) {
                    __half2 hv = __floats2half2_rn(xn.x, xn.y);
                    char* xd = (char*)xsm + (p ^ 1) * 2304 + xoffb;
                    *reinterpret_cast<__half2*>(xd) = hv;
                    *reinterpret_cast<__half2*>(xd + DUPX) = hv;
                }
                // cell-0 RK4; final h0 also published to h0o[s&1]
                rk4_g<MM_WG0H, MM_WREC0, 1>(wb, its, xin0, xg0, hst, (char*)hA[0],
                                            (char*)hA[1], addr_hA, cu, hi, hoff,
                                            (char*)h0o[s & 1]);
                p ^= 1;
            }
        } else {
            if (s > 0) {
                // cell-1 input projections from h0(s-1)
                float ci[2][4] = {}, cg[2][4] = {};
                mma_phase_g<8, MM_WIN1, MM_WG1X>(wb, addr_h0[(s - 1) & 1], ci, cg);
                float xin1[4], xg1[4];
#pragma unroll
                for (int i = 0; i < 4; ++i) {
                    xin1[i] = csel(ci, hi, i);
                    xg1[i] = csel(cg, hi, i) + xgc[i];  // xgc = bg1 for B
                }
                // cell-1 RK4
                rk4_g<MM_WG1H, MM_WREC1, 2>(wb, its, xin1, xg1, hst, (char*)hB[0],
                                            (char*)hB[1], addr_hB, cu, hi, hoff,
                                            nullptr);
            }
        }
        __syncthreads();
    }

    // ---- classifier: sigmoid(relu(h1 @ W1^T + b1) @ W2^T + b2) ----
    if (!isA) {
#pragma unroll
        for (int i = 0; i < 4; ++i) {
            int j = wg * 16 + (i >> 1) * 8 + 2 * (lane & 3) + (i & 1);
            st0[b * 128 + j] = hst[i];
        }
    }
    __syncthreads();
    if (tid < 128) {
        const int bb = tid >> 5, ln = tid & 31;
        float a0 = b1[ln], a1 = b1[ln + 32];
        const float* hv = st0 + bb * 128;
        const float* w0 = W1 + ln * 128;
        const float* w1 = W1 + (ln + 32) * 128;
#pragma unroll 8
        for (int k = 0; k < 128; ++k) {
            float h = hv[k];
            a0 = fmaf(h, w0[k], a0);
            a1 = fmaf(h, w1[k], a1);
        }
        a0 = fmaxf(a0, 0.f);
        a1 = fmaxf(a1, 0.f);
        float pr = a0 * __ldg(W2 + ln) + a1 * __ldg(W2 + ln + 32);
#pragma unroll
        for (int off = 16; off; off >>= 1)
            pr += __shfl_xor_sync(0xffffffffu, pr, off);
        if (ln == 0) out[b0g + bb] = sigm(pr + b2[0]);
    }
}

extern "C" void kernel_launch(void* const* d_in, const int* in_sizes, int n_in,
                              void* d_out, int out_size) {
    const float* seq   = (const float*)d_in[0];
    const float* ctx   = (const float*)d_in[1];
    const float* tau0  = (const float*)d_in[2];
    const float* Win0  = (const float*)d_in[3];
    const float* Wrec0 = (const float*)d_in[4];
    const float* Wg0   = (const float*)d_in[5];
    const float* bg0   = (const float*)d_in[6];
    const float* tau1  = (const float*)d_in[7];
    const float* Win1  = (const float*)d_in[8];
    const float* Wrec1 = (const float*)d_in[9];
    const float* Wg1   = (const float*)d_in[10];
    const float* bg1   = (const float*)d_in[11];
    const float* W1    = (const float*)d_in[12];
    const float* b1    = (const float*)d_in[13];
    const float* W2    = (const float*)d_in[14];
    const float* b2    = (const float*)d_in[15];
    float* out = (float*)d_out;

    prep_weights<<<(MM_TOTAL + 8192 + 255) / 256, 256>>>(Win0, Wg0, Wrec0, Win1,
                                                         Wrec1, Wg1);
    ltc_recurrent<<<128, 512>>>(seq, ctx, tau0, bg0, tau1, bg1, W1, b1, W2, b2, out);
}

// round 16
// speedup vs baseline: 1.5177x; 1.5177x over previous
#include <cuda_runtime.h>
#include <cuda_fp16.h>
#include <cstdint>
#include <cstddef>

#define S_LEN 512

// A-fragment-linear weights (u32 lane-regs) for mma.m16n8k16 with A = W.
// For mat, k-tile q, m-tile t: u32 at base + (q*8 + t)*128 + l*4 + r holds
// halves {W[j][k], W[j][k+1]} with j = t*16 + l/4 + (r&1)*8,
// k = q*16 + 2*(l%4) + (r>>1)*8.
#define MM_WG0H  0
#define MM_WREC0 8192
#define MM_WIN1  16384
#define MM_WG1X  24576
#define MM_WG1H  32768
#define MM_WREC1 40960
#define MM_WIN0S 49152
#define MM_WG0S  53248
#define MM_TOTAL 57344

__device__ __align__(16) uint32_t g_Wm[MM_TOTAL];
// ctx mats fp32 row-major [j][32]: [0]=Win0 ctx part, [4096]=Wg0 ctx part
__device__ __align__(16) float g_Wc[2 * 4096];

#define HSTB 272  // h smem row stride bytes (136 halves), rows = batch (8)
#define XSTB 144  // x smem row stride bytes (72 halves), rows = batch (8)

__device__ __forceinline__ float sigm(float x) {
    return __fdividef(1.0f, 1.0f + __expf(-x));
}
__device__ __forceinline__ float fast_tanh(float x) {
    float ax = fabsf(x);
    float e = __expf(ax + ax);
    float t = 1.0f - __fdividef(2.0f, e + 1.0f);
    return copysignf(t, x);
}
// gate = sigmoid(tanh(z)); sigmoid of t in [-1,1] via degree-7 odd polynomial
__device__ __forceinline__ float gate_fn(float z) {
    float t = fast_tanh(z);
    float t2 = t * t;
    float p = fmaf(t2, -2.00134e-4f, 2.0833333e-3f);
    p = fmaf(t2, p, -2.0833334e-2f);
    p = fmaf(t2, p, 0.25f);
    return fmaf(t, p, 0.5f);
}

// ---------------- weight prep: A-fragment-linear fp16 + fp32 ctx ----------------
__global__ void __launch_bounds__(256) prep_weights(
    const float* __restrict__ Win0, const float* __restrict__ Wg0,
    const float* __restrict__ Wrec0, const float* __restrict__ Win1,
    const float* __restrict__ Wrec1, const float* __restrict__ Wg1) {
    int idx = blockIdx.x * 256 + threadIdx.x;
    if (idx < MM_TOTAL) {
        int mat, rem;
        if (idx < 49152) {
            mat = idx >> 13;
            rem = idx & 8191;
        } else {
            mat = 6 + ((idx - 49152) >> 12);
            rem = (idx - 49152) & 4095;
        }
        int q = rem >> 10;          // k-tile
        int rest = rem & 1023;
        int t = rest >> 7;          // m-tile (j)
        int le = rest & 127;
        int l = le >> 2, r = le & 3;
        int j = t * 16 + (l >> 2) + (r & 1) * 8;
        int k = q * 16 + 2 * (l & 3) + (r >> 1) * 8;
        float f0, f1;
        switch (mat) {
            case 0: f0 = Wg0[j * 224 + 96 + k]; f1 = Wg0[j * 224 + 97 + k]; break;
            case 1: f0 = Wrec0[j * 128 + k]; f1 = Wrec0[j * 128 + k + 1]; break;
            case 2: f0 = Win1[j * 128 + k]; f1 = Win1[j * 128 + k + 1]; break;
            case 3: f0 = Wg1[j * 256 + k]; f1 = Wg1[j * 256 + k + 1]; break;
            case 4: f0 = Wg1[j * 256 + 128 + k]; f1 = Wg1[j * 256 + 129 + k]; break;
            case 5: f0 = Wrec1[j * 128 + k]; f1 = Wrec1[j * 128 + k + 1]; break;
            case 6: f0 = Win0[j * 96 + k]; f1 = Win0[j * 96 + k + 1]; break;
            default: f0 = Wg0[j * 224 + k]; f1 = Wg0[j * 224 + k + 1]; break;
        }
        uint32_t u = (uint32_t)__half_as_ushort(__float2half_rn(f0)) |
                     ((uint32_t)__half_as_ushort(__float2half_rn(f1)) << 16);
        g_Wm[idx] = u;
    } else if (idx < MM_TOTAL + 8192) {
        int r2 = idx - MM_TOTAL;
        int m = r2 >> 12, a = r2 & 4095;
        int j = a >> 5, k = a & 31;
        g_Wc[r2] = m ? Wg0[j * 224 + 64 + k] : Win0[j * 96 + 64 + k];
    }
}

// ---------------- mma primitives ----------------
__device__ __forceinline__ void ldsm2(uint32_t addr, uint32_t& r0, uint32_t& r1) {
    asm volatile("ldmatrix.sync.aligned.m8n8.x2.shared.b16 {%0,%1}, [%2];"
                 : "=r"(r0), "=r"(r1)
                 : "r"(addr));
}
__device__ __forceinline__ void mma16816(float* c, uint32_t a0, uint32_t a1,
                                         uint32_t a2, uint32_t a3, uint32_t b0,
                                         uint32_t b1) {
    asm volatile(
        "mma.sync.aligned.m16n8k16.row.col.f32.f16.f16.f32 "
        "{%0,%1,%2,%3}, {%4,%5,%6,%7}, {%8,%9}, {%0,%1,%2,%3};"
        : "+f"(c[0]), "+f"(c[1]), "+f"(c[2]), "+f"(c[3])
        : "r"(a0), "r"(a1), "r"(a2), "r"(a3), "r"(b0), "r"(b1));
}

// Group dual-matmul phase, swapped operands: D[j][b] = W @ h^T. Warp covers
// m-tiles {2*wg, 2*wg+1} of both mats (wa2 has the 2*wg fold). h/x in smem as
// [batch-row][k]; B-frag = plain ldmatrix.x2 (b16x2 pairs run along k).
// KT = K/16.
template <int KT, int OFFA, int OFFB>
__device__ __forceinline__ void mma_phase_g(const uint32_t* __restrict__ wa2,
                                            uint32_t baddr, float cA[2][4],
                                            float cB[2][4]) {
#pragma unroll
    for (int q = 0; q < KT; ++q) {
        uint32_t b0, b1;
        ldsm2(baddr + q * 32, b0, b1);
#pragma unroll
        for (int tt = 0; tt < 2; ++tt) {
            uint4 A1 = __ldg(reinterpret_cast<const uint4*>(wa2 + OFFA + q * 1024 +
                                                            tt * 128));
            uint4 A2 = __ldg(reinterpret_cast<const uint4*>(wa2 + OFFB + q * 1024 +
                                                            tt * 128));
            mma16816(cA[tt], A1.x, A1.y, A1.z, A1.w, b0, b1);
            mma16816(cB[tt], A2.x, A2.y, A2.z, A2.w, b0, b1);
        }
    }
}

// Slot mapping (lane l, slot i in 0..7): tt = i>>2, cidx = i&3 where
// c0..c3 = {row l/4 col nb, row l/4 col nb+1, row l/4+8 col nb, ... col nb+1}
// wait: PTX C layout: c0=(l/4, 2(l%4)), c1=(l/4, 2(l%4)+1), c2=(l/4+8, 2(l%4)),
// c3=(l/4+8, 2(l%4)+1). So cidx = jr*2 + s2 with jr = row-half, s2 = col sub.
//   j = wg*32 + (l>>2) + ((i>>1)&1)*8 + (i>>2)*16
//   b = 2*(l&3) + (i&1)       (real iff (l&3) < 2)
// store byte offset = hoff0 + (i&1)*HSTB + ((i>>1)&1)*16 + (i>>2)*32

// RK4 for one cell run by ONE 128-thread group (named barrier BARID). Active
// lanes ((l&3)<2) own 8 real (j, b) slots; h rows 4-7 stay zero (N padding).
template <int OFFG, int OFFR, int BARID>
__device__ __forceinline__ void rk4_g(const uint32_t* __restrict__ wa2,
                                      const float* it, const float* xin,
                                      const float* xg, float* hst, char* nb0,
                                      char* nb1, const uint32_t baddr[2], int& cu,
                                      bool act, int hoff0, char* hout) {
    float ka[8] = {0, 0, 0, 0, 0, 0, 0, 0};
    float ht[8];
#pragma unroll
    for (int i = 0; i < 8; ++i) ht[i] = hst[i];
#pragma unroll
    for (int sub = 0; sub < 4; ++sub) {
        float cg[2][4] = {}, cr[2][4] = {};
        mma_phase_g<8, OFFG, OFFR>(wa2, baddr[cu], cg, cr);
        const float kw = (sub == 0 || sub == 3) ? 1.f : 2.f;
        const float cv = (sub < 2) ? 0.5f : 1.f;
        if (act) {
            char* dst = cu ? nb0 : nb1;  // next buffer = cu^1
#pragma unroll
            for (int i = 0; i < 8; ++i) {
                const int cidx = ((i >> 1) & 1) * 2 + (i & 1);
                float gate = gate_fn(cg[i >> 2][cidx] + xg[i]);
                float kv = fmaf(gate, cr[i >> 2][cidx], fmaf(-ht[i], it[i], xin[i]));
                ka[i] = fmaf(kw, kv, ka[i]);
                float nh = (sub < 3) ? fmaf(cv, kv, hst[i])
                                     : fast_tanh(fmaf(ka[i], 0.16666667f, hst[i]));
                ht[i] = nh;
                const int off =
                    hoff0 + (i & 1) * HSTB + ((i >> 1) & 1) * 16 + (i >> 2) * 32;
                __half hv = __float2half(nh);
                *reinterpret_cast<__half*>(dst + off) = hv;
                if (sub == 3 && hout) *reinterpret_cast<__half*>(hout + off) = hv;
            }
        }
        asm volatile("bar.sync %0, 128;" ::"r"(BARID) : "memory");
        cu ^= 1;
    }
#pragma unroll
    for (int i = 0; i < 8; ++i) hst[i] = ht[i];
}

// ---------------- persistent recurrence: 128 CTAs x 256 threads ----------------
// Warp-specialized cell pipeline: warps 0-3 (group A, bar 1) run the cell-0
// chain; warps 4-7 (group B, bar 2) run cell-1 one step behind via a parity
// double-buffer. Swapped-operand MMA: M = j (full 16), N = batch (4 real +
// 4 zero-pad) — halves the tensor work vs batch-as-M.
__global__ void __launch_bounds__(256, 1)
ltc_recurrent(const float* __restrict__ seq, const float* __restrict__ ctx,
              const float* __restrict__ tau0, const float* __restrict__ bg0,
              const float* __restrict__ tau1, const float* __restrict__ bg1,
              const float* __restrict__ W1, const float* __restrict__ b1,
              const float* __restrict__ W2, const float* __restrict__ b2,
              float* __restrict__ out) {
    __shared__ __align__(16) __half hA[2][8 * 136];   // cell-0 RK4 ping-pong
    __shared__ __align__(16) __half hB[2][8 * 136];   // cell-1 RK4 ping-pong
    __shared__ __align__(16) __half h0o[2][8 * 136];  // A->B handoff (parity)
    __shared__ __align__(16) __half xsm[2][8 * 72];   // x double buffer
    __shared__ __align__(16) float xcf[128];
    __shared__ __align__(16) float st0[512];
    const int tid = threadIdx.x, lane = tid & 31;
    const bool isA = tid < 128;
    const int wg = (tid >> 5) & 3;
    const int b0g = blockIdx.x * 4;
    const bool act = (lane & 3) < 2;

    // zero all fp16 operand buffers (batch rows 4-7 stay zero = N padding)
    {
        __half z = __float2half(0.f);
        for (int i = tid; i < 2 * 8 * 136; i += 256) {
            reinterpret_cast<__half*>(hA)[i] = z;
            reinterpret_cast<__half*>(hB)[i] = z;
            reinterpret_cast<__half*>(h0o)[i] = z;
        }
        for (int i = tid; i < 2 * 8 * 72; i += 256)
            reinterpret_cast<__half*>(xsm)[i] = z;
    }
    if (tid < 128) xcf[tid] = ctx[(size_t)(b0g + (tid >> 5)) * 32 + (tid & 31)];
    __syncthreads();

    // per-lane slot params (active lanes): slot i -> (j, b) per mapping above
    float its[8], xinc[8] = {0, 0, 0, 0, 0, 0, 0, 0},
                  xgc[8] = {0, 0, 0, 0, 0, 0, 0, 0};
    const int hoff0 = 2 * (lane & 3) * HSTB + (wg * 32 + (lane >> 2)) * 2;
#pragma unroll
    for (int i = 0; i < 8; ++i) {
        int j = wg * 32 + (lane >> 2) + ((i >> 1) & 1) * 8 + (i >> 2) * 16;
        int b = 2 * (lane & 3) + (i & 1);
        const float* taup = isA ? tau0 : tau1;
        its[i] = __fdividef(1.f, log1pf(__expf(taup[j])) + 1.f);
        if (act) {
            if (isA) {
                float ai = 0.f, ag = 0.f;
                for (int k = 0; k < 32; ++k) {
                    float xv = xcf[b * 32 + k];
                    ai = fmaf(xv, __ldg(&g_Wc[j * 32 + k]), ai);
                    ag = fmaf(xv, __ldg(&g_Wc[4096 + j * 32 + k]), ag);
                }
                xinc[i] = ai;
                xgc[i] = ag + bg0[j];
            } else {
                xgc[i] = bg1[j];  // xgc = bg1 bias for group B
            }
        }
    }

    // x staging: A threads stage one half2 each: batch row tid>>5, k pair tid&31
    const int xb = (tid >> 5) & 3;
    const int xk2 = tid & 31;
    const float* seqp = seq + ((size_t)(b0g + xb) * S_LEN) * 64 + 2 * xk2;
    const int xoffb = xb * XSTB + xk2 * 4;
    if (isA) {
        float2 v = *reinterpret_cast<const float2*>(seqp);
        *reinterpret_cast<__half2*>((char*)xsm + xoffb) = __floats2half2_rn(v.x, v.y);
    }
    __syncthreads();

    // ldmatrix B (h/x) row addresses: lanes 0-7 -> matrix 0 rows (k block +0),
    // lanes 8-15 -> matrix 1 rows (k block +16B); others replicate (unused).
    const uint32_t brow = (uint32_t)(lane & 7);
    const uint32_t bsel = (uint32_t)((lane >> 3) & 1);
    const uint32_t boffh = brow * HSTB + bsel * 16;
    const uint32_t boffx = brow * XSTB + bsel * 16;
    const uint32_t bA0 = (uint32_t)__cvta_generic_to_shared(hA);
    const uint32_t bB0 = (uint32_t)__cvta_generic_to_shared(hB);
    const uint32_t bH0 = (uint32_t)__cvta_generic_to_shared(h0o);
    const uint32_t bX0 = (uint32_t)__cvta_generic_to_shared(xsm);
    const uint32_t addr_hA[2] = {bA0 + boffh, bA0 + 2176 + boffh};
    const uint32_t addr_hB[2] = {bB0 + boffh, bB0 + 2176 + boffh};
    const uint32_t addr_h0[2] = {bH0 + boffh, bH0 + 2176 + boffh};
    const uint32_t addr_x[2] = {bX0 + boffx, bX0 + 1152 + boffx};

    // warp's A-fragment (W) base: m-tiles {2*wg, 2*wg+1} folded in
    const uint32_t* wa2 = g_Wm + wg * 256 + lane * 4;

    float hst[8] = {0, 0, 0, 0, 0, 0, 0, 0};
    int cu = 0, p = 0;

    for (int s = 0; s <= S_LEN; ++s) {
        if (isA) {
            if (s < S_LEN) {
                // prefetch x(s+1)
                float2 xn = {0.f, 0.f};
                const bool hasn = (s + 1 < S_LEN);
                if (hasn)
                    xn = *reinterpret_cast<const float2*>(seqp + (size_t)(s + 1) * 64);
                // cell-0 input projections from x(s) (64-k: 4 k-tiles)
                float ci[2][4] = {}, cg[2][4] = {};
                mma_phase_g<4, MM_WIN0S, MM_WG0S>(wa2, addr_x[p], ci, cg);
                float xin0[8], xg0[8];
#pragma unroll
                for (int i = 0; i < 8; ++i) {
                    const int cidx = ((i >> 1) & 1) * 2 + (i & 1);
                    xin0[i] = ci[i >> 2][cidx] + xinc[i];
                    xg0[i] = cg[i >> 2][cidx] + xgc[i];
                }
                // stage x(s+1) (readers: next step's A proj, after 4 bar-1s)
                if (hasn)
                    *reinterpret_cast<__half2*>((char*)xsm + (p ^ 1) * 1152 + xoffb) =
                        __floats2half2_rn(xn.x, xn.y);
                // cell-0 RK4; final h0 also published to h0o[s&1]
                rk4_g<MM_WG0H, MM_WREC0, 1>(wa2, its, xin0, xg0, hst, (char*)hA[0],
                                            (char*)hA[1], addr_hA, cu, act, hoff0,
                                            (char*)h0o[s & 1]);
                p ^= 1;
            }
        } else {
            if (s > 0) {
                // cell-1 input projections from h0(s-1)
                float ci[2][4] = {}, cg[2][4] = {};
                mma_phase_g<8, MM_WIN1, MM_WG1X>(wa2, addr_h0[(s - 1) & 1], ci, cg);
                float xin1[8], xg1[8];
#pragma unroll
                for (int i = 0; i < 8; ++i) {
                    const int cidx = ((i >> 1) & 1) * 2 + (i & 1);
                    xin1[i] = ci[i >> 2][cidx];
                    xg1[i] = cg[i >> 2][cidx] + xgc[i];  // xgc = bg1 for B
                }
                // cell-1 RK4
                rk4_g<MM_WG1H, MM_WREC1, 2>(wa2, its, xin1, xg1, hst, (char*)hB[0],
                                            (char*)hB[1], addr_hB, cu, act, hoff0,
                                            nullptr);
            }
        }
        __syncthreads();
    }

    // ---- classifier: sigmoid(relu(h1 @ W1^T + b1) @ W2^T + b2) ----
    if (!isA && act) {
#pragma unroll
        for (int i = 0; i < 8; ++i) {
            int j = wg * 32 + (lane >> 2) + ((i >> 1) & 1) * 8 + (i >> 2) * 16;
            int b = 2 * (lane & 3) + (i & 1);
            st0[b * 128 + j] = hst[i];
        }
    }
    __syncthreads();
    if (tid < 128) {
        const int bb = tid >> 5, ln = tid & 31;
        float a0 = b1[ln], a1 = b1[ln + 32];
        const float* hv = st0 + bb * 128;
        const float* w0 = W1 + ln * 128;
        const float* w1 = W1 + (ln + 32) * 128;
#pragma unroll 8
        for (int k = 0; k < 128; ++k) {
            float h = hv[k];
            a0 = fmaf(h, w0[k], a0);
            a1 = fmaf(h, w1[k], a1);
        }
        a0 = fmaxf(a0, 0.f);
        a1 = fmaxf(a1, 0.f);
        float pr = a0 * __ldg(W2 + ln) + a1 * __ldg(W2 + ln + 32);
#pragma unroll
        for (int off = 16; off; off >>= 1)
            pr += __shfl_xor_sync(0xffffffffu, pr, off);
        if (ln == 0) out[b0g + bb] = sigm(pr + b2[0]);
    }
}

extern "C" void kernel_launch(void* const* d_in, const int* in_sizes, int n_in,
                              void* d_out, int out_size) {
    const float* seq   = (const float*)d_in[0];
    const float* ctx   = (const float*)d_in[1];
    const float* tau0  = (const float*)d_in[2];
    const float* Win0  = (const float*)d_in[3];
    const float* Wrec0 = (const float*)d_in[4];
    const float* Wg0   = (const float*)d_in[5];
    const float* bg0   = (const float*)d_in[6];
    const float* tau1  = (const float*)d_in[7];
    const float* Win1  = (const float*)d_in[8];
    const float* Wrec1 = (const float*)d_in[9];
    const float* Wg1   = (const float*)d_in[10];
    const float* bg1   = (const float*)d_in[11];
    const float* W1    = (const float*)d_in[12];
    const float* b1    = (const float*)d_in[13];
    const float* W2    = (const float*)d_in[14];
    const float* b2    = (const float*)d_in[15];
    float* out = (float*)d_out;

    prep_weights<<<(MM_TOTAL + 8192 + 255) / 256, 256>>>(Win0, Wg0, Wrec0, Win1,
                                                         Wrec1, Wg1);
    ltc_recurrent<<<128, 256>>>(seq, ctx, tau0, bg0, tau1, bg1, W1, b1, W2, b2, out);
}

// round 17
// speedup vs baseline: 1.5693x; 1.0340x over previous
#include <cuda_runtime.h>
#include <cuda_fp16.h>
#include <cstdint>
#include <cstddef>

#define S_LEN 512

// A-fragment-linear weights (u32 lane-regs) for mma.m16n8k16 with A = W.
// For mat, k-tile q, m-tile t: u32 at base + (q*8 + t)*128 + l*4 + r holds
// halves {W[j][k], W[j][k+1]} with j = t*16 + l/4 + (r&1)*8,
// k = q*16 + 2*(l%4) + (r>>1)*8.
#define MM_WG0H  0
#define MM_WREC0 8192
#define MM_WIN1  16384
#define MM_WG1X  24576
#define MM_WG1H  32768
#define MM_WREC1 40960
#define MM_WIN0S 49152
#define MM_WG0S  53248
#define MM_TOTAL 57344

__device__ __align__(16) uint32_t g_Wm[MM_TOTAL];
// ctx mats fp32 row-major [j][32]: [0]=Win0 ctx part, [4096]=Wg0 ctx part
__device__ __align__(16) float g_Wc[2 * 4096];

#define HSTB 272  // h smem row stride bytes (136 halves), rows = batch (8)
#define XSTB 144  // x smem row stride bytes (72 halves), rows = batch (8)
#define DUPB_H (4 * HSTB)  // batch-dup row offset (rows 4-7 = copies of 0-3)
#define DUPB_X (4 * XSTB)

__device__ __forceinline__ float sigm(float x) {
    return __fdividef(1.0f, 1.0f + __expf(-x));
}
__device__ __forceinline__ float fast_tanh(float x) {
    float ax = fabsf(x);
    float e = __expf(ax + ax);
    float t = 1.0f - __fdividef(2.0f, e + 1.0f);
    return copysignf(t, x);
}
// gate = sigmoid(tanh(z)); sigmoid of t in [-1,1] via degree-7 odd polynomial
__device__ __forceinline__ float gate_fn(float z) {
    float t = fast_tanh(z);
    float t2 = t * t;
    float p = fmaf(t2, -2.00134e-4f, 2.0833333e-3f);
    p = fmaf(t2, p, -2.0833334e-2f);
    p = fmaf(t2, p, 0.25f);
    return fmaf(t, p, 0.5f);
}

// ---------------- weight prep: A-fragment-linear fp16 + fp32 ctx ----------------
__global__ void __launch_bounds__(256) prep_weights(
    const float* __restrict__ Win0, const float* __restrict__ Wg0,
    const float* __restrict__ Wrec0, const float* __restrict__ Win1,
    const float* __restrict__ Wrec1, const float* __restrict__ Wg1) {
    int idx = blockIdx.x * 256 + threadIdx.x;
    if (idx < MM_TOTAL) {
        int mat, rem;
        if (idx < 49152) {
            mat = idx >> 13;
            rem = idx & 8191;
        } else {
            mat = 6 + ((idx - 49152) >> 12);
            rem = (idx - 49152) & 4095;
        }
        int q = rem >> 10;          // k-tile
        int rest = rem & 1023;
        int t = rest >> 7;          // m-tile (j)
        int le = rest & 127;
        int l = le >> 2, r = le & 3;
        int j = t * 16 + (l >> 2) + (r & 1) * 8;
        int k = q * 16 + 2 * (l & 3) + (r >> 1) * 8;
        float f0, f1;
        switch (mat) {
            case 0: f0 = Wg0[j * 224 + 96 + k]; f1 = Wg0[j * 224 + 97 + k]; break;
            case 1: f0 = Wrec0[j * 128 + k]; f1 = Wrec0[j * 128 + k + 1]; break;
            case 2: f0 = Win1[j * 128 + k]; f1 = Win1[j * 128 + k + 1]; break;
            case 3: f0 = Wg1[j * 256 + k]; f1 = Wg1[j * 256 + k + 1]; break;
            case 4: f0 = Wg1[j * 256 + 128 + k]; f1 = Wg1[j * 256 + 129 + k]; break;
            case 5: f0 = Wrec1[j * 128 + k]; f1 = Wrec1[j * 128 + k + 1]; break;
            case 6: f0 = Win0[j * 96 + k]; f1 = Win0[j * 96 + k + 1]; break;
            default: f0 = Wg0[j * 224 + k]; f1 = Wg0[j * 224 + k + 1]; break;
        }
        uint32_t u = (uint32_t)__half_as_ushort(__float2half_rn(f0)) |
                     ((uint32_t)__half_as_ushort(__float2half_rn(f1)) << 16);
        g_Wm[idx] = u;
    } else if (idx < MM_TOTAL + 8192) {
        int r2 = idx - MM_TOTAL;
        int m = r2 >> 12, a = r2 & 4095;
        int j = a >> 5, k = a & 31;
        g_Wc[r2] = m ? Wg0[j * 224 + 64 + k] : Win0[j * 96 + 64 + k];
    }
}

// ---------------- mma primitives ----------------
__device__ __forceinline__ void ldsm2(uint32_t addr, uint32_t& r0, uint32_t& r1) {
    asm volatile("ldmatrix.sync.aligned.m8n8.x2.shared.b16 {%0,%1}, [%2];"
                 : "=r"(r0), "=r"(r1)
                 : "r"(addr));
}
__device__ __forceinline__ void mma16816(float* c, uint32_t a0, uint32_t a1,
                                         uint32_t a2, uint32_t a3, uint32_t b0,
                                         uint32_t b1) {
    asm volatile(
        "mma.sync.aligned.m16n8k16.row.col.f32.f16.f16.f32 "
        "{%0,%1,%2,%3}, {%4,%5,%6,%7}, {%8,%9}, {%0,%1,%2,%3};"
        : "+f"(c[0]), "+f"(c[1]), "+f"(c[2]), "+f"(c[3])
        : "r"(a0), "r"(a1), "r"(a2), "r"(a3), "r"(b0), "r"(b1));
}

// Group dual-matmul phase, swapped operands: D[j][b] = W @ h^T. Warp covers
// m-tiles {2*wg, 2*wg+1} of both mats. h/x smem rows 0-3 = batches, rows 4-7 =
// duplicates; B-frag = plain ldmatrix.x2. KT = K/16.
template <int KT, int OFFA, int OFFB>
__device__ __forceinline__ void mma_phase_g(const uint32_t* __restrict__ wa2,
                                            uint32_t baddr, float cA[2][4],
                                            float cB[2][4]) {
#pragma unroll
    for (int q = 0; q < KT; ++q) {
        uint32_t b0, b1;
        ldsm2(baddr + q * 32, b0, b1);
#pragma unroll
        for (int tt = 0; tt < 2; ++tt) {
            uint4 A1 = __ldg(reinterpret_cast<const uint4*>(wa2 + OFFA + q * 1024 +
                                                            tt * 128));
            uint4 A2 = __ldg(reinterpret_cast<const uint4*>(wa2 + OFFB + q * 1024 +
                                                            tt * 128));
            mma16816(cA[tt], A1.x, A1.y, A1.z, A1.w, b0, b1);
            mma16816(cB[tt], A2.x, A2.y, A2.z, A2.w, b0, b1);
        }
    }
}

// Slot mapping with N-dup (cols 4-7 duplicate batches 0-3):
//   lane l: jr = (l>>1)&1 (owned j row-half), b = 2*(l&1) + s2
//   slot i = tt*2 + s2 (tt = m-tile, s2 = col sub), cidx = jr*2 + s2
//   j = wg*32 + (l>>2) + jr*8 + tt*16
// C cols for this lane are 2*(l&3)+s2; low lanes (l&3<2) see real cols b,
// high lanes see dup cols b+4 with identical values — both equal D[j][b].

// RK4 for one cell run by ONE 128-thread group (named barrier BARID). Every
// lane owns 4 (j, b) slots; new h stored to row b and dup row b+4.
template <int OFFG, int OFFR, int BARID>
__device__ __forceinline__ void rk4_g(const uint32_t* __restrict__ wa2,
                                      const float* it, const float* xin,
                                      const float* xg, float* hst, char* nb0,
                                      char* nb1, const uint32_t baddr[2], int& cu,
                                      int jr, int hoff0, char* hout) {
    float ka[4] = {0, 0, 0, 0};
    float ht[4] = {hst[0], hst[1], hst[2], hst[3]};
#pragma unroll
    for (int sub = 0; sub < 4; ++sub) {
        float cg[2][4] = {}, cr[2][4] = {};
        mma_phase_g<8, OFFG, OFFR>(wa2, baddr[cu], cg, cr);
        const float kw = (sub == 0 || sub == 3) ? 1.f : 2.f;
        const float cv = (sub < 2) ? 0.5f : 1.f;
        char* dst = cu ? nb0 : nb1;  // next buffer = cu^1
#pragma unroll
        for (int i = 0; i < 4; ++i) {
            const int tt = i >> 1, s2 = i & 1;
            const int cidx = jr * 2 + s2;
            float gate = gate_fn(cg[tt][cidx] + xg[i]);
            float kv = fmaf(gate, cr[tt][cidx], fmaf(-ht[i], it[i], xin[i]));
            ka[i] = fmaf(kw, kv, ka[i]);
            float nh = (sub < 3) ? fmaf(cv, kv, hst[i])
                                 : fast_tanh(fmaf(ka[i], 0.16666667f, hst[i]));
            ht[i] = nh;
            // store to (row b, col j) and dup row b+4
            const int off = hoff0 + s2 * HSTB + tt * 32;
            __half hv = __float2half(nh);
            *reinterpret_cast<__half*>(dst + off) = hv;
            *reinterpret_cast<__half*>(dst + off + DUPB_H) = hv;
            if (sub == 3 && hout) {
                *reinterpret_cast<__half*>(hout + off) = hv;
                *reinterpret_cast<__half*>(hout + off + DUPB_H) = hv;
            }
        }
        asm volatile("bar.sync %0, 128;" ::"r"(BARID) : "memory");
        cu ^= 1;
    }
#pragma unroll
    for (int i = 0; i < 4; ++i) hst[i] = ht[i];
}

// ---------------- persistent recurrence: 128 CTAs x 256 threads ----------------
// Warp-specialized cell pipeline: warps 0-3 (group A, bar 1) run the cell-0
// chain; warps 4-7 (group B, bar 2) run cell-1 one step behind via a parity
// double-buffer. Swapped-operand MMA (M = j, N = batch) with N-dup: batch
// rows/cols 4-7 duplicate 0-3 so all 32 lanes own 4 valid slots each.
__global__ void __launch_bounds__(256, 1)
ltc_recurrent(const float* __restrict__ seq, const float* __restrict__ ctx,
              const float* __restrict__ tau0, const float* __restrict__ bg0,
              const float* __restrict__ tau1, const float* __restrict__ bg1,
              const float* __restrict__ W1, const float* __restrict__ b1,
              const float* __restrict__ W2, const float* __restrict__ b2,
              float* __restrict__ out) {
    __shared__ __align__(16) __half hA[2][8 * 136];   // cell-0 RK4 ping-pong
    __shared__ __align__(16) __half hB[2][8 * 136];   // cell-1 RK4 ping-pong
    __shared__ __align__(16) __half h0o[2][8 * 136];  // A->B handoff (parity)
    __shared__ __align__(16) __half xsm[2][8 * 72];   // x double buffer
    __shared__ __align__(16) float xcf[128];
    __shared__ __align__(16) float st0[512];
    const int tid = threadIdx.x, lane = tid & 31;
    const bool isA = tid < 128;
    const int wg = (tid >> 5) & 3;
    const int b0g = blockIdx.x * 4;
    const int jr = (lane >> 1) & 1;   // owned j row-half
    const int bb0 = 2 * (lane & 1);   // owned batch base (b = bb0 + s2)

    // zero all fp16 operand buffers once (dup rows overwritten each phase)
    {
        __half z = __float2half(0.f);
        for (int i = tid; i < 2 * 8 * 136; i += 256) {
            reinterpret_cast<__half*>(hA)[i] = z;
            reinterpret_cast<__half*>(hB)[i] = z;
            reinterpret_cast<__half*>(h0o)[i] = z;
        }
        for (int i = tid; i < 2 * 8 * 72; i += 256)
            reinterpret_cast<__half*>(xsm)[i] = z;
    }
    if (tid < 128) xcf[tid] = ctx[(size_t)(b0g + (tid >> 5)) * 32 + (tid & 31)];
    __syncthreads();

    // per-lane slot params: slot i -> j = wg*32 + (lane>>2) + jr*8 + (i>>1)*16,
    //                                 b = bb0 + (i&1)
    float its[4], xinc[4] = {0, 0, 0, 0}, xgc[4] = {0, 0, 0, 0};
    const int hoff0 = bb0 * HSTB + (wg * 32 + (lane >> 2) + jr * 8) * 2;
#pragma unroll
    for (int i = 0; i < 4; ++i) {
        int j = wg * 32 + (lane >> 2) + jr * 8 + (i >> 1) * 16;
        int b = bb0 + (i & 1);
        const float* taup = isA ? tau0 : tau1;
        its[i] = __fdividef(1.f, log1pf(__expf(taup[j])) + 1.f);
        if (isA) {
            float ai = 0.f, ag = 0.f;
            for (int k = 0; k < 32; ++k) {
                float xv = xcf[b * 32 + k];
                ai = fmaf(xv, __ldg(&g_Wc[j * 32 + k]), ai);
                ag = fmaf(xv, __ldg(&g_Wc[4096 + j * 32 + k]), ag);
            }
            xinc[i] = ai;
            xgc[i] = ag + bg0[j];
        } else {
            xgc[i] = bg1[j];  // xgc = bg1 bias for group B
        }
    }

    // x staging: A threads stage one half2 each to row xb and dup row xb+4
    const int xb = (tid >> 5) & 3;
    const int xk2 = tid & 31;
    const float* seqp = seq + ((size_t)(b0g + xb) * S_LEN) * 64 + 2 * xk2;
    const int xoffb = xb * XSTB + xk2 * 4;
    if (isA) {
        float2 v = *reinterpret_cast<const float2*>(seqp);
        __half2 hv = __floats2half2_rn(v.x, v.y);
        *reinterpret_cast<__half2*>((char*)xsm + xoffb) = hv;
        *reinterpret_cast<__half2*>((char*)xsm + xoffb + DUPB_X) = hv;
    }
    __syncthreads();

    // ldmatrix B (h/x) row addresses: lanes 0-7 -> matrix 0 rows, lanes 8-15 ->
    // matrix 1 (k block +16B)
    const uint32_t brow = (uint32_t)(lane & 7);
    const uint32_t bsel = (uint32_t)((lane >> 3) & 1);
    const uint32_t boffh = brow * HSTB + bsel * 16;
    const uint32_t boffx = brow * XSTB + bsel * 16;
    const uint32_t bA0 = (uint32_t)__cvta_generic_to_shared(hA);
    const uint32_t bB0 = (uint32_t)__cvta_generic_to_shared(hB);
    const uint32_t bH0 = (uint32_t)__cvta_generic_to_shared(h0o);
    const uint32_t bX0 = (uint32_t)__cvta_generic_to_shared(xsm);
    const uint32_t addr_hA[2] = {bA0 + boffh, bA0 + 2176 + boffh};
    const uint32_t addr_hB[2] = {bB0 + boffh, bB0 + 2176 + boffh};
    const uint32_t addr_h0[2] = {bH0 + boffh, bH0 + 2176 + boffh};
    const uint32_t addr_x[2] = {bX0 + boffx, bX0 + 1152 + boffx};

    // warp's A-fragment (W) base: m-tiles {2*wg, 2*wg+1} folded in
    const uint32_t* wa2 = g_Wm + wg * 256 + lane * 4;

    float hst[4] = {0, 0, 0, 0};
    int cu = 0, p = 0;

    for (int s = 0; s <= S_LEN; ++s) {
        if (isA) {
            if (s < S_LEN) {
                // prefetch x(s+1)
                float2 xn = {0.f, 0.f};
                const bool hasn = (s + 1 < S_LEN);
                if (hasn)
                    xn = *reinterpret_cast<const float2*>(seqp + (size_t)(s + 1) * 64);
                // cell-0 input projections from x(s) (64-k: 4 k-tiles)
                float ci[2][4] = {}, cg[2][4] = {};
                mma_phase_g<4, MM_WIN0S, MM_WG0S>(wa2, addr_x[p], ci, cg);
                float xin0[4], xg0[4];
#pragma unroll
                for (int i = 0; i < 4; ++i) {
                    const int cidx = jr * 2 + (i & 1);
                    xin0[i] = ci[i >> 1][cidx] + xinc[i];
                    xg0[i] = cg[i >> 1][cidx] + xgc[i];
                }
                // stage x(s+1) (readers: next step's A proj, after 4 bar-1s)
                if (hasn) {
                    __half2 hv = __floats2half2_rn(xn.x, xn.y);
                    char* xd = (char*)xsm + (p ^ 1) * 1152 + xoffb;
                    *reinterpret_cast<__half2*>(xd) = hv;
                    *reinterpret_cast<__half2*>(xd + DUPB_X) = hv;
                }
                // cell-0 RK4; final h0 also published to h0o[s&1]
                rk4_g<MM_WG0H, MM_WREC0, 1>(wa2, its, xin0, xg0, hst, (char*)hA[0],
                                            (char*)hA[1], addr_hA, cu, jr, hoff0,
                                            (char*)h0o[s & 1]);
                p ^= 1;
            }
        } else {
            if (s > 0) {
                // cell-1 input projections from h0(s-1)
                float ci[2][4] = {}, cg[2][4] = {};
                mma_phase_g<8, MM_WIN1, MM_WG1X>(wa2, addr_h0[(s - 1) & 1], ci, cg);
                float xin1[4], xg1[4];
#pragma unroll
                for (int i = 0; i < 4; ++i) {
                    const int cidx = jr * 2 + (i & 1);
                    xin1[i] = ci[i >> 1][cidx];
                    xg1[i] = cg[i >> 1][cidx] + xgc[i];  // xgc = bg1 for B
                }
                // cell-1 RK4
                rk4_g<MM_WG1H, MM_WREC1, 2>(wa2, its, xin1, xg1, hst, (char*)hB[0],
                                            (char*)hB[1], addr_hB, cu, jr, hoff0,
                                            nullptr);
            }
        }
        __syncthreads();
    }

    // ---- classifier: sigmoid(relu(h1 @ W1^T + b1) @ W2^T + b2) ----
    if (!isA) {
#pragma unroll
        for (int i = 0; i < 4; ++i) {
            int j = wg * 32 + (lane >> 2) + jr * 8 + (i >> 1) * 16;
            int b = bb0 + (i & 1);
            st0[b * 128 + j] = hst[i];
        }
    }
    __syncthreads();
    if (tid < 128) {
        const int bc = tid >> 5, ln = tid & 31;
        float a0 = b1[ln], a1 = b1[ln + 32];
        const float* hv = st0 + bc * 128;
        const float* w0 = W1 + ln * 128;
        const float* w1 = W1 + (ln + 32) * 128;
#pragma unroll 8
        for (int k = 0; k < 128; ++k) {
            float h = hv[k];
            a0 = fmaf(h, w0[k], a0);
            a1 = fmaf(h, w1[k], a1);
        }
        a0 = fmaxf(a0, 0.f);
        a1 = fmaxf(a1, 0.f);
        float pr = a0 * __ldg(W2 + ln) + a1 * __ldg(W2 + ln + 32);
#pragma unroll
        for (int off = 16; off; off >>= 1)
            pr += __shfl_xor_sync(0xffffffffu, pr, off);
        if (ln == 0) out[b0g + bc] = sigm(pr + b2[0]);
    }
}

extern "C" void kernel_launch(void* const* d_in, const int* in_sizes, int n_in,
                              void* d_out, int out_size) {
    const float* seq   = (const float*)d_in[0];
    const float* ctx   = (const float*)d_in[1];
    const float* tau0  = (const float*)d_in[2];
    const float* Win0  = (const float*)d_in[3];
    const float* Wrec0 = (const float*)d_in[4];
    const float* Wg0   = (const float*)d_in[5];
    const float* bg0   = (const float*)d_in[6];
    const float* tau1  = (const float*)d_in[7];
    const float* Win1  = (const float*)d_in[8];
    const float* Wrec1 = (const float*)d_in[9];
    const float* Wg1   = (const float*)d_in[10];
    const float* bg1   = (const float*)d_in[11];
    const float* W1    = (const float*)d_in[12];
    const float* b1    = (const float*)d_in[13];
    const float* W2    = (const float*)d_in[14];
    const float* b2    = (const float*)d_in[15];
    float* out = (float*)d_out;

    prep_weights<<<(MM_TOTAL + 8192 + 255) / 256, 256>>>(Win0, Wg0, Wrec0, Win1,
                                                         Wrec1, Wg1);
    ltc_recurrent<<<128, 256>>>(seq, ctx, tau0, bg0, tau1, bg1, W1, b1, W2, b2, out);
}